// round 16
// baseline (speedup 1.0000x reference)
#include <cuda_runtime.h>
#include <cuda_bf16.h>
#include <math_constants.h>
#include <stdint.h>

// Problem constants
#define BATCH   96
#define NW      10
#define NTOK    144            // window tokens
#define CDIM    192
#define HEADS   6
#define DH      32
#define MTOT    (BATCH*NW*NTOK)        // 138240
#define NHEADTOT (BATCH*NW*HEADS)      // 5760
#define NN2     (NTOK*NTOK)            // 20736
#define BIASTOT (NW*HEADS*NN2)         // 1244160
#define MASKTOT (BATCH*NN2)            // 1990656
#define QKVN    (3*CDIM)               // 576
#define SCALE   0.17677669529663687f   // 32^-0.5
#define LOG2E   1.4426950408889634f

// ---------------- cp.async helpers (Ampere-baseline PTX) -------------------
__device__ __forceinline__ uint32_t s2u(const void* p) {
    uint32_t a;
    asm("{ .reg .u64 t; cvta.to.shared.u64 t, %1; cvt.u32.u64 %0, t; }"
        : "=r"(a) : "l"(p));
    return a;
}
__device__ __forceinline__ void cp_async16(uint32_t s, const void* g) {
    asm volatile("cp.async.cg.shared.global [%0], [%1], 16;" :: "r"(s), "l"(g));
}
#define CP_COMMIT() asm volatile("cp.async.commit_group;" ::: "memory")
#define CP_WAIT0()  asm volatile("cp.async.wait_group 0;" ::: "memory")

__device__ __forceinline__ float ex2(float x) {
    float y;
    asm("ex2.approx.f32 %0, %1;" : "=f"(y) : "f"(x));
    return y;
}

// -------- scratch (device globals; no runtime allocation allowed) ----------
__device__ float g_q[NHEADTOT * NTOK * DH];   // [head][n][d], pre-scaled by SCALE*LOG2E
__device__ float g_k[NHEADTOT * NTOK * DH];
__device__ float g_v[NHEADTOT * NTOK * DH];
__device__ float g_att[MTOT * CDIM];          // attention output, [B,nW,N,C]
__device__ float g_bias[BIASTOT];             // [w][h][i*N+j], pre-scaled by LOG2E
__device__ float g_maskx[MASKTOT];            // mask * LOG2E

// ---------------------------------------------------------------------------
// K0a: materialize relative-position bias (pre-scaled by LOG2E)
// ---------------------------------------------------------------------------
__global__ void build_bias_kernel(const float* __restrict__ bias_table,
                                  const int* __restrict__ pidx) {
    int idx = blockIdx.x * blockDim.x + threadIdx.x;
    if (idx >= BIASTOT) return;
    int wh = idx / NN2;
    int ij = idx - wh * NN2;
    g_bias[idx] = bias_table[pidx[ij] * (NW * HEADS) + wh] * LOG2E;
}

// K0b: pre-scale mask by LOG2E
__global__ void scale_mask_kernel(const float* __restrict__ mask) {
    int idx = blockIdx.x * blockDim.x + threadIdx.x;
    if (idx >= MASKTOT) return;
    g_maskx[idx] = mask[idx] * LOG2E;
}

// ---------------------------------------------------------------------------
// Pipelined wide-N SGEMM: BM=64, BN=192, BK=16, 384 threads, 8x4 microtile.
// ---------------------------------------------------------------------------
#define WBM 64
#define WBN 192
#define WBK 16
#define NKT (CDIM / WBK)    // 12

// ---------------- K1: QKV GEMM + scatter to g_q/g_k/g_v --------------------
__global__ __launch_bounds__(384)
void qkv_gemm3_kernel(const float* __restrict__ X,
                      const float* __restrict__ W,
                      const float* __restrict__ bqkv) {
    __shared__ float As[2][WBK][WBM];    // 8 KB
    __shared__ float Bs[2][WBK][WBN];    // 24 KB

    const int tid = threadIdx.x;
    const int w   = tid >> 5;
    const int l   = tid & 31;
    const int tx  = (l & 15) + 16 * (w % 3);   // 0..47
    const int ty  = (l >> 4) + 2 * (w / 3);    // 0..7
    const int m0  = blockIdx.x * WBM;
    const int n0  = blockIdx.y * WBN;

    const int bk0 = tid / 48,         bc0 = tid - bk0 * 48;
    const int bk1 = (tid + 384) / 48, bc1 = (tid + 384) - bk1 * 48;
    const float* bg0 = W + (size_t)bk0 * QKVN + n0 + bc0 * 4;
    const float* bg1 = W + (size_t)bk1 * QKVN + n0 + bc1 * 4;

    const int ar = tid >> 2, ac4 = tid & 3;
    const float* ag = X + (size_t)(m0 + ar) * CDIM + ac4 * 4;

    float acc[8][4];
    #pragma unroll
    for (int r = 0; r < 8; ++r)
        #pragma unroll
        for (int c = 0; c < 4; ++c) acc[r][c] = 0.f;

    float4 areg;

    if (tid < 256) areg = *(const float4*)ag;
    cp_async16(s2u(&Bs[0][bk0][bc0 * 4]), bg0);
    cp_async16(s2u(&Bs[0][bk1][bc1 * 4]), bg1);
    CP_COMMIT();
    if (tid < 256) {
        As[0][ac4 * 4 + 0][ar] = areg.x;
        As[0][ac4 * 4 + 1][ar] = areg.y;
        As[0][ac4 * 4 + 2][ar] = areg.z;
        As[0][ac4 * 4 + 3][ar] = areg.w;
    }
    CP_WAIT0();
    __syncthreads();

    for (int kt = 0; kt < NKT; ++kt) {
        const int cur = kt & 1;
        const int nxt = cur ^ 1;
        if (kt < NKT - 1) {
            const int k0 = (kt + 1) * WBK;
            if (tid < 256) areg = *(const float4*)(ag + k0);
            cp_async16(s2u(&Bs[nxt][bk0][bc0 * 4]), bg0 + (size_t)k0 * QKVN);
            cp_async16(s2u(&Bs[nxt][bk1][bc1 * 4]), bg1 + (size_t)k0 * QKVN);
            CP_COMMIT();
        }

        #pragma unroll
        for (int k = 0; k < WBK; ++k) {
            float4 a0 = *(const float4*)&As[cur][k][ty * 8];
            float4 a1 = *(const float4*)&As[cur][k][ty * 8 + 4];
            float4 bb = *(const float4*)&Bs[cur][k][tx * 4];
            float arr[8] = {a0.x, a0.y, a0.z, a0.w, a1.x, a1.y, a1.z, a1.w};
            float bc[4]  = {bb.x, bb.y, bb.z, bb.w};
            #pragma unroll
            for (int r = 0; r < 8; ++r)
                #pragma unroll
                for (int c = 0; c < 4; ++c)
                    acc[r][c] = fmaf(arr[r], bc[c], acc[r][c]);
        }

        if (kt < NKT - 1) {
            if (tid < 256) {
                As[nxt][ac4 * 4 + 0][ar] = areg.x;
                As[nxt][ac4 * 4 + 1][ar] = areg.y;
                As[nxt][ac4 * 4 + 2][ar] = areg.z;
                As[nxt][ac4 * 4 + 3][ar] = areg.w;
            }
            CP_WAIT0();
        }
        __syncthreads();
    }

    // ---- epilogue: q pre-scaled by SCALE*LOG2E (softmax folding) ----
    const int cg = n0 + tx * 4;
    const int t  = cg / CDIM;              // 0=q,1=k,2=v
    const int rem = cg - t * CDIM;
    const int h  = rem >> 5;
    const int d  = rem & 31;
    float* dstbase = (t == 0) ? g_q : (t == 1) ? g_k : g_v;
    const float sc = (t == 0) ? SCALE * LOG2E : 1.0f;
    float4 bq = *(const float4*)(bqkv + cg);

    #pragma unroll
    for (int r = 0; r < 8; ++r) {
        int m  = m0 + ty * 8 + r;
        int bw = m / NTOK;
        int nn = m - bw * NTOK;
        float4 val;
        val.x = (acc[r][0] + bq.x) * sc;
        val.y = (acc[r][1] + bq.y) * sc;
        val.z = (acc[r][2] + bq.z) * sc;
        val.w = (acc[r][3] + bq.w) * sc;
        *(float4*)&dstbase[(size_t)((bw * HEADS + h) * NTOK + nn) * DH + d] = val;
    }
}

// ---------------- K3: projection GEMM -> d_out (pipelined) -----------------
__global__ __launch_bounds__(384)
void proj_gemm3_kernel(const float* __restrict__ Wp,
                       const float* __restrict__ bp,
                       float* __restrict__ out) {
    __shared__ float As[2][WBK][WBM];
    __shared__ float Bs[2][WBK][WBN];

    const int tid = threadIdx.x;
    const int w   = tid >> 5;
    const int l   = tid & 31;
    const int tx  = (l & 15) + 16 * (w % 3);
    const int ty  = (l >> 4) + 2 * (w / 3);
    const int m0  = blockIdx.x * WBM;

    const int bk0 = tid / 48,         bc0 = tid - bk0 * 48;
    const int bk1 = (tid + 384) / 48, bc1 = (tid + 384) - bk1 * 48;
    const float* bg0 = Wp + (size_t)bk0 * CDIM + bc0 * 4;
    const float* bg1 = Wp + (size_t)bk1 * CDIM + bc1 * 4;

    const int ar = tid >> 2, ac4 = tid & 3;
    const float* ag = g_att + (size_t)(m0 + ar) * CDIM + ac4 * 4;

    float acc[8][4];
    #pragma unroll
    for (int r = 0; r < 8; ++r)
        #pragma unroll
        for (int c = 0; c < 4; ++c) acc[r][c] = 0.f;

    float4 areg;

    if (tid < 256) areg = *(const float4*)ag;
    cp_async16(s2u(&Bs[0][bk0][bc0 * 4]), bg0);
    cp_async16(s2u(&Bs[0][bk1][bc1 * 4]), bg1);
    CP_COMMIT();
    if (tid < 256) {
        As[0][ac4 * 4 + 0][ar] = areg.x;
        As[0][ac4 * 4 + 1][ar] = areg.y;
        As[0][ac4 * 4 + 2][ar] = areg.z;
        As[0][ac4 * 4 + 3][ar] = areg.w;
    }
    CP_WAIT0();
    __syncthreads();

    for (int kt = 0; kt < NKT; ++kt) {
        const int cur = kt & 1;
        const int nxt = cur ^ 1;
        if (kt < NKT - 1) {
            const int k0 = (kt + 1) * WBK;
            if (tid < 256) areg = *(const float4*)(ag + k0);
            cp_async16(s2u(&Bs[nxt][bk0][bc0 * 4]), bg0 + (size_t)k0 * CDIM);
            cp_async16(s2u(&Bs[nxt][bk1][bc1 * 4]), bg1 + (size_t)k0 * CDIM);
            CP_COMMIT();
        }

        #pragma unroll
        for (int k = 0; k < WBK; ++k) {
            float4 a0 = *(const float4*)&As[cur][k][ty * 8];
            float4 a1 = *(const float4*)&As[cur][k][ty * 8 + 4];
            float4 bb = *(const float4*)&Bs[cur][k][tx * 4];
            float arr[8] = {a0.x, a0.y, a0.z, a0.w, a1.x, a1.y, a1.z, a1.w};
            float bc[4]  = {bb.x, bb.y, bb.z, bb.w};
            #pragma unroll
            for (int r = 0; r < 8; ++r)
                #pragma unroll
                for (int c = 0; c < 4; ++c)
                    acc[r][c] = fmaf(arr[r], bc[c], acc[r][c]);
        }

        if (kt < NKT - 1) {
            if (tid < 256) {
                As[nxt][ac4 * 4 + 0][ar] = areg.x;
                As[nxt][ac4 * 4 + 1][ar] = areg.y;
                As[nxt][ac4 * 4 + 2][ar] = areg.z;
                As[nxt][ac4 * 4 + 3][ar] = areg.w;
            }
            CP_WAIT0();
        }
        __syncthreads();
    }

    const int cg = tx * 4;
    float4 bq = *(const float4*)(bp + cg);
    #pragma unroll
    for (int r = 0; r < 8; ++r) {
        int m = m0 + ty * 8 + r;
        float4 val;
        val.x = acc[r][0] + bq.x;
        val.y = acc[r][1] + bq.y;
        val.z = acc[r][2] + bq.z;
        val.w = acc[r][3] + bq.w;
        *(float4*)(out + (size_t)m * CDIM + cg) = val;
    }
}

// ---------------------------------------------------------------------------
// K2: fused attention, one-pass softmax (scores bounded; no max needed).
// One block per (b,w,h) head, 160 threads, K/V + staged bias/mask in smem.
// q pre-scaled by SCALE*LOG2E; bias/mask pre-scaled by LOG2E -> p = ex2(s).
// ---------------------------------------------------------------------------
__global__ __launch_bounds__(160)
void attn_kernel() {
    __shared__ float Ks[NTOK * DH];        // 18432 B
    __shared__ float Vs[NTOK * DH];        // 18432 B
    __shared__ float BMs[NTOK * 17];       // 9792 B

    const int head = blockIdx.x;           // = b*60 + w*6 + h
    const int h    = head % HEADS;
    const int bw   = head / HEADS;
    const int b    = head / (NW * HEADS);
    const int t    = threadIdx.x;

    const float* kb = g_k + (size_t)head * NTOK * DH;
    const float* vb = g_v + (size_t)head * NTOK * DH;
    const float* qb = g_q + (size_t)head * NTOK * DH;
    const float* biasWH = g_bias + (size_t)(head % (NW * HEADS)) * NN2;
    const float* maskB  = g_maskx + (size_t)b * NN2;

    for (int idx = t; idx < NTOK * DH / 4; idx += 160) {
        ((float4*)Ks)[idx] = ((const float4*)kb)[idx];
        ((float4*)Vs)[idx] = ((const float4*)vb)[idx];
    }

    float q[DH];
    if (t < NTOK) {
        const float4* qr = (const float4*)(qb + t * DH);
        #pragma unroll
        for (int d4 = 0; d4 < 8; ++d4) {
            float4 v4 = qr[d4];
            q[d4 * 4 + 0] = v4.x; q[d4 * 4 + 1] = v4.y;
            q[d4 * 4 + 2] = v4.z; q[d4 * 4 + 3] = v4.w;
        }
    }

    float o[DH];
    #pragma unroll
    for (int d = 0; d < DH; ++d) o[d] = 0.f;
    float srun = 0.f;

    for (int jt = 0; jt < 9; ++jt) {       // 9 tiles of 16 keys
        __syncthreads();                   // also covers initial K/V load
        for (int idx = t; idx < 576; idx += 160) {
            int row = idx >> 2;
            int c4  = idx & 3;
            int gi  = row * NTOK + jt * 16 + c4 * 4;
            float4 bb = *(const float4*)(biasWH + gi);
            float4 mm = *(const float4*)(maskB + gi);
            float* dst = &BMs[row * 17 + c4 * 4];
            dst[0] = bb.x + mm.x; dst[1] = bb.y + mm.y;
            dst[2] = bb.z + mm.z; dst[3] = bb.w + mm.w;
        }
        __syncthreads();

        if (t < NTOK) {
            #pragma unroll
            for (int jj = 0; jj < 16; ++jj) {
                const int j = jt * 16 + jj;
                const float4* kr = (const float4*)(Ks + j * DH);
                float a0 = 0.f, a1 = 0.f, a2 = 0.f, a3 = 0.f;
                #pragma unroll
                for (int d4 = 0; d4 < 8; ++d4) {
                    float4 kv = kr[d4];                  // broadcast LDS
                    a0 = fmaf(q[d4 * 4 + 0], kv.x, a0);
                    a1 = fmaf(q[d4 * 4 + 1], kv.y, a1);
                    a2 = fmaf(q[d4 * 4 + 2], kv.z, a2);
                    a3 = fmaf(q[d4 * 4 + 3], kv.w, a3);
                }
                const float p = ex2((a0 + a1) + (a2 + a3) + BMs[t * 17 + jj]);
                srun += p;
                const float4* vr = (const float4*)(Vs + j * DH);
                #pragma unroll
                for (int d4 = 0; d4 < 8; ++d4) {
                    float4 vv = vr[d4];                  // broadcast LDS
                    o[d4 * 4 + 0] = fmaf(p, vv.x, o[d4 * 4 + 0]);
                    o[d4 * 4 + 1] = fmaf(p, vv.y, o[d4 * 4 + 1]);
                    o[d4 * 4 + 2] = fmaf(p, vv.z, o[d4 * 4 + 2]);
                    o[d4 * 4 + 3] = fmaf(p, vv.w, o[d4 * 4 + 3]);
                }
            }
        }
    }

    if (t < NTOK) {
        const float inv = 1.0f / srun;
        float* op = g_att + ((size_t)bw * NTOK + t) * CDIM + h * DH;
        #pragma unroll
        for (int d4 = 0; d4 < 8; ++d4) {
            float4 v4;
            v4.x = o[d4 * 4 + 0] * inv; v4.y = o[d4 * 4 + 1] * inv;
            v4.z = o[d4 * 4 + 2] * inv; v4.w = o[d4 * 4 + 3] * inv;
            *(float4*)(op + d4 * 4) = v4;
        }
    }
}

// ---------------------------------------------------------------------------
extern "C" void kernel_launch(void* const* d_in, const int* in_sizes, int n_in,
                              void* d_out, int out_size) {
    const float* x          = (const float*)d_in[0];
    const float* mask       = (const float*)d_in[1];
    const float* w_qkv      = (const float*)d_in[2];
    const float* b_qkv      = (const float*)d_in[3];
    const float* w_proj     = (const float*)d_in[4];
    const float* b_proj     = (const float*)d_in[5];
    const float* bias_table = (const float*)d_in[6];
    const int*   pidx       = (const int*)d_in[7];
    float* out = (float*)d_out;

    build_bias_kernel<<<(BIASTOT + 255) / 256, 256>>>(bias_table, pidx);
    scale_mask_kernel<<<(MASKTOT + 255) / 256, 256>>>(mask);
    qkv_gemm3_kernel<<<dim3(MTOT / WBM, QKVN / WBN), 384>>>(x, w_qkv, b_qkv);
    attn_kernel<<<NHEADTOT, 160>>>();
    proj_gemm3_kernel<<<MTOT / WBM, 384>>>(w_proj, b_proj, out);
}